// round 1
// baseline (speedup 1.0000x reference)
#include <cuda_runtime.h>

// LSTM: B=4096, T=512, F=32, H=60. Persistent per-CTA recurrence over 32 batch rows.
// Weights (92x240 fp32, gate-interleaved) resident in SMEM. c in registers, h in SMEM.

#define T_STEPS 512
#define F_IN    32
#define H_DIM   60
#define K_DIM   92      // F_IN + H_DIM
#define KPAD    96      // padded A row stride (floats)
#define NCOL    240     // 4*H
#define BB      32      // batch rows per CTA
#define THREADS 256
#define FORGET_BIAS 1.0f

// smem layout (floats): W[92*240] | A[32*96] | bias[240]
#define W_ELEMS   (K_DIM * NCOL)          // 22080
#define A_ELEMS   (BB * KPAD)             // 3072
#define B_ELEMS   (NCOL)                  // 240
#define SMEM_FLOATS (W_ELEMS + A_ELEMS + B_ELEMS)
#define SMEM_BYTES  (SMEM_FLOATS * 4)     // 101,568 B

__device__ __forceinline__ float sigmoid_f(float x) {
    // 1/(1+e^-x); exp overflow to inf gives RCP->0, correct saturation.
    return __fdividef(1.0f, 1.0f + __expf(-x));
}
__device__ __forceinline__ float tanh_f(float x) {
    // overflow-safe: work on |x|, restore sign. e in (0,1].
    float e = __expf(-2.0f * fabsf(x));
    float r = __fdividef(1.0f - e, 1.0f + e);
    return copysignf(r, x);
}

__global__ void __launch_bounds__(THREADS, 1)
lstm_persistent_kernel(const float* __restrict__ x,
                       const float* __restrict__ kernel,   // [92][240], gate order i,j,f,o
                       const float* __restrict__ bias,     // [240]
                       const float* __restrict__ dense_w,  // [60]
                       const float* __restrict__ dense_b,  // [1]
                       float* __restrict__ out,            // [B]
                       int Btotal)
{
    extern __shared__ float smem[];
    float* Wsm = smem;                       // [k][hcol*4 + g]
    float* Asm = smem + W_ELEMS;             // [row][KPAD]: k 0..31 = x_t, 32..91 = h
    float* bsm = smem + W_ELEMS + A_ELEMS;   // [hcol*4 + g]

    const int tx   = threadIdx.x;
    const int row0 = blockIdx.x * BB;

    // ---- load + gate-interleave weights: kernel[k][g*60+hcol] -> Wsm[k*240 + hcol*4 + g]
    for (int idx = tx; idx < W_ELEMS; idx += THREADS) {
        int k = idx / NCOL, c = idx % NCOL;
        int hcol = c >> 2, g = c & 3;
        Wsm[idx] = kernel[k * NCOL + g * H_DIM + hcol];
    }
    for (int idx = tx; idx < NCOL; idx += THREADS) {
        int hcol = idx >> 2, g = idx & 3;
        bsm[idx] = bias[g * H_DIM + hcol];
    }
    // zero activation tile (h starts at 0; x region will be overwritten)
    for (int idx = tx; idx < A_ELEMS; idx += THREADS) Asm[idx] = 0.0f;
    __syncthreads();

    // ---- thread mapping: rgroup in [0,4), hcol in [0,64) (active < 60)
    const int rg   = tx >> 6;
    const int hcol = tx & 63;
    const bool active = (hcol < H_DIM);

    float4 bias4 = make_float4(0.f, 0.f, 0.f, 0.f);
    if (active) bias4 = *(const float4*)&bsm[hcol * 4];

    float c_state[8];
#pragma unroll
    for (int r = 0; r < 8; r++) c_state[r] = 0.0f;

    // ---- x prefetch setup: each thread owns 4 of the 1024 tile elements
    const float* xp[4];
    int sidx[4];
    bool xvalid[4];
#pragma unroll
    for (int i = 0; i < 4; i++) {
        int idx = tx + i * THREADS;         // [0,1024)
        int r = idx >> 5, f = idx & 31;
        xvalid[i] = (row0 + r) < Btotal;
        xp[i] = xvalid[i] ? (x + (size_t)(row0 + r) * (T_STEPS * F_IN) + f)
                          : x;  // dummy, never stored
        sidx[i] = r * KPAD + f;
    }
    float xr[4];
#pragma unroll
    for (int i = 0; i < 4; i++) xr[i] = xvalid[i] ? xp[i][0] : 0.0f;

    const float4* Wv   = (const float4*)Wsm;          // idx = k*60 + hcol
    const float*  Arow = Asm + rg * 8 * KPAD;

    float hnew[8];

    for (int t = 0; t < T_STEPS; ++t) {
        // store x_t tile (x region disjoint from h region)
#pragma unroll
        for (int i = 0; i < 4; i++)
            if (xvalid[i]) Asm[sidx[i]] = xr[i];
        __syncthreads();

        // prefetch next x_t (LDG latency overlaps GEMM below)
        if (t < T_STEPS - 1) {
#pragma unroll
            for (int i = 0; i < 4; i++)
                if (xvalid[i]) xr[i] = xp[i][(t + 1) * F_IN];
        }

        if (active) {
            float4 acc[8];
#pragma unroll
            for (int r = 0; r < 8; r++) acc[r] = bias4;

#pragma unroll 1
            for (int k4 = 0; k4 < K_DIM / 4; k4++) {
                float4 av[8];
#pragma unroll
                for (int r = 0; r < 8; r++)
                    av[r] = *(const float4*)(Arow + r * KPAD + 4 * k4);
#pragma unroll
                for (int kk = 0; kk < 4; kk++) {
                    float4 w = Wv[(4 * k4 + kk) * H_DIM + hcol];
#pragma unroll
                    for (int r = 0; r < 8; r++) {
                        float a = ((const float*)&av[r])[kk];
                        acc[r].x = fmaf(a, w.x, acc[r].x);
                        acc[r].y = fmaf(a, w.y, acc[r].y);
                        acc[r].z = fmaf(a, w.z, acc[r].z);
                        acc[r].w = fmaf(a, w.w, acc[r].w);
                    }
                }
            }

            // pointwise LSTM update: acc = (i, j, f, o) for this hidden unit
#pragma unroll
            for (int r = 0; r < 8; r++) {
                float ig = sigmoid_f(acc[r].x);
                float jg = tanh_f   (acc[r].y);
                float fg = sigmoid_f(acc[r].z + FORGET_BIAS);
                float og = sigmoid_f(acc[r].w);
                float c2 = c_state[r] * fg + ig * jg;
                c_state[r] = c2;
                hnew[r] = tanh_f(c2) * og;
            }
        }
        __syncthreads();  // all GEMM reads of A done before h overwrite

        if (active) {
#pragma unroll
            for (int r = 0; r < 8; r++)
                Asm[(rg * 8 + r) * KPAD + F_IN + hcol] = hnew[r];
        }
        // next iteration's x-store targets the disjoint x region; the GEMM that
        // reads this h waits at the next __syncthreads above.
    }
    __syncthreads();

    // final dense: out[b] = h[b,:] . dense_w + dense_b
    if (tx < BB && (row0 + tx) < Btotal) {
        float s = dense_b[0];
        const float* hrow = Asm + tx * KPAD + F_IN;
#pragma unroll
        for (int k = 0; k < H_DIM; k++) s = fmaf(hrow[k], dense_w[k], s);
        out[row0 + tx] = s;
    }
}

extern "C" void kernel_launch(void* const* d_in, const int* in_sizes, int n_in,
                              void* d_out, int out_size)
{
    const float* x        = (const float*)d_in[0];
    const float* kernel   = (const float*)d_in[1];
    const float* bias     = (const float*)d_in[2];
    const float* dense_w  = (const float*)d_in[3];
    const float* dense_b  = (const float*)d_in[4];
    float* out = (float*)d_out;

    int Btotal = in_sizes[0] / (T_STEPS * F_IN);   // 4096
    int grid   = (Btotal + BB - 1) / BB;           // 128

    cudaFuncSetAttribute(lstm_persistent_kernel,
                         cudaFuncAttributeMaxDynamicSharedMemorySize, SMEM_BYTES);

    lstm_persistent_kernel<<<grid, THREADS, SMEM_BYTES>>>(
        x, kernel, bias, dense_w, dense_b, out, Btotal);
}